// round 8
// baseline (speedup 1.0000x reference)
#include <cuda_runtime.h>
#include <cuda_bf16.h>
#include <cstdint>

#define MEM_SIZE 262144
#define FEAT 512
#define TOPK 256
#define BATCH 128
#define CAND_CAP 4096

typedef unsigned long long u64;
typedef unsigned int u32;

// ---------------- scratch (static __device__, no allocation) ----------------
__device__ __align__(16) float g_qn[BATCH * FEAT];
__device__ __align__(16) __nv_bfloat16 g_qbf[BATCH * FEAT];
__device__ __align__(16) __nv_bfloat16 g_sbf[(size_t)BATCH * MEM_SIZE];  // approx scores, bf16, 64 MB
__device__ int   g_cand_idx[BATCH * CAND_CAP];
__device__ int   g_cand_cnt[BATCH];
__device__ int   g_topk_idx[BATCH * TOPK];

// ---------------- helpers ----------------
__device__ __forceinline__ uint32_t smem_u32(const void* p) {
    uint32_t a;
    asm("{ .reg .u64 t; cvta.to.shared.u64 t, %1; cvt.u32.u64 %0, t; }" : "=r"(a) : "l"(p));
    return a;
}
__device__ __forceinline__ u32 f2bf2(float lo, float hi) {
    u32 r; asm("cvt.rn.bf16x2.f32 %0, %1, %2;" : "=r"(r) : "f"(hi), "f"(lo)); return r;
}
__device__ __forceinline__ u32 swz(u32 off) { return off ^ ((off >> 3) & 0x70u); }

__device__ __forceinline__ void ldsm_x4(u32* r, u32 addr) {
    asm volatile("ldmatrix.sync.aligned.m8n8.x4.shared.b16 {%0,%1,%2,%3}, [%4];"
                 : "=r"(r[0]), "=r"(r[1]), "=r"(r[2]), "=r"(r[3]) : "r"(addr));
}
__device__ __forceinline__ void mma16816(float* c, const u32* a, u32 b0, u32 b1) {
    asm volatile(
        "mma.sync.aligned.m16n8k16.row.col.f32.bf16.bf16.f32 "
        "{%0,%1,%2,%3}, {%4,%5,%6,%7}, {%8,%9}, {%0,%1,%2,%3};"
        : "+f"(c[0]), "+f"(c[1]), "+f"(c[2]), "+f"(c[3])
        : "r"(a[0]), "r"(a[1]), "r"(a[2]), "r"(a[3]), "r"(b0), "r"(b1));
}
__device__ __forceinline__ void cp_async16(u32 dst, const void* src) {
    u64 g = (u64)__cvta_generic_to_global(src);
    asm volatile("cp.async.cg.shared.global [%0], [%1], 16;" :: "r"(dst), "l"(g) : "memory");
}
#define CP_COMMIT() asm volatile("cp.async.commit_group;" ::: "memory")
#define CP_WAIT0()  asm volatile("cp.async.wait_group 0;" ::: "memory")

// ---------------- 1) query L2 normalize + bf16 copy ----------------
__global__ void qnorm_kernel(const float* __restrict__ q) {
    int b = blockIdx.x;
    const float* row = q + (size_t)b * FEAT;
    float s = 0.f;
    for (int i = threadIdx.x; i < FEAT; i += blockDim.x) { float v = row[i]; s += v * v; }
    __shared__ float red[32];
    int lane = threadIdx.x & 31, wid = threadIdx.x >> 5;
    #pragma unroll
    for (int o = 16; o > 0; o >>= 1) s += __shfl_xor_sync(0xFFFFFFFFu, s, o);
    if (lane == 0) red[wid] = s;
    __syncthreads();
    if (wid == 0) {
        s = (lane < (int)(blockDim.x >> 5)) ? red[lane] : 0.f;
        #pragma unroll
        for (int o = 16; o > 0; o >>= 1) s += __shfl_xor_sync(0xFFFFFFFFu, s, o);
        if (lane == 0) red[0] = s;
    }
    __syncthreads();
    float inv = 1.0f / sqrtf(red[0]);
    for (int i = threadIdx.x; i < FEAT; i += blockDim.x) {
        float v = row[i] * inv;
        g_qn[(size_t)b * FEAT + i] = v;
        g_qbf[(size_t)b * FEAT + i] = __float2bfloat16(v);
    }
}

// ---------------- 2) bf16 mma.sync score GEMM ----------------
#define BK 64
#define A_TILE 16384
#define B_TILE 16384
#define GEMM_SMEM (2 * A_TILE + 2 * B_TILE)   // 64 KB

__global__ __launch_bounds__(256, 2) void score_gemm_mma(const float* __restrict__ sk) {
    extern __shared__ __align__(1024) char smem[];
    const int tid = threadIdx.x;
    const int wid = tid >> 5, lane = tid & 31;
    const int wm = (wid & 1) * 64;
    const int wn = (wid >> 1) * 32;
    const int n0 = blockIdx.x * 128;
    const u32 sbase = smem_u32(smem);

    float acc[4][4][4];
    #pragma unroll
    for (int i = 0; i < 4; i++)
        #pragma unroll
        for (int j = 0; j < 4; j++)
            #pragma unroll
            for (int k = 0; k < 4; k++) acc[i][j][k] = 0.f;

    float4 st[4][2];

    auto ldgB = [&](int c) {
        #pragma unroll
        for (int it = 0; it < 4; it++) {
            int id = tid + it * 256;
            int r = id >> 3, c32 = id & 7;
            const float4* p = reinterpret_cast<const float4*>(
                sk + (size_t)(n0 + r) * FEAT + c * BK + c32 * 8);
            st[it][0] = p[0]; st[it][1] = p[1];
        }
    };
    auto stsB = [&](int buf) {
        char* bb = smem + 2 * A_TILE + buf * B_TILE;
        #pragma unroll
        for (int it = 0; it < 4; it++) {
            int id = tid + it * 256;
            int r = id >> 3, c32 = id & 7;
            uint4 o;
            o.x = f2bf2(st[it][0].x, st[it][0].y);
            o.y = f2bf2(st[it][0].z, st[it][0].w);
            o.z = f2bf2(st[it][1].x, st[it][1].y);
            o.w = f2bf2(st[it][1].z, st[it][1].w);
            *reinterpret_cast<uint4*>(bb + swz(r * 128 + c32 * 16)) = o;
        }
    };
    auto cpA = [&](int c, int buf) {
        const char* src0 = reinterpret_cast<const char*>(g_qbf);
        u32 dst0 = sbase + buf * A_TILE;
        #pragma unroll
        for (int it = 0; it < 4; it++) {
            int id = tid + it * 256;
            int r = id >> 3, c16 = id & 7;
            cp_async16(dst0 + swz(r * 128 + c16 * 16),
                       src0 + r * 1024 + c * 128 + c16 * 16);
        }
    };

    const int jj = lane >> 3;
    const int akoff = (jj >= 2) ? 16 : 0;
    const int amoff = (jj & 1) * 8;
    const int bnoff = (jj >= 2) ? 8 : 0;
    const int bkoff = (jj & 1) * 16;
    auto compute = [&](int buf) {
        u32 abase = sbase + buf * A_TILE;
        u32 bbase = sbase + 2 * A_TILE + buf * B_TILE;
        #pragma unroll
        for (int ks = 0; ks < 4; ks++) {
            u32 a[4][4], b[2][4];
            #pragma unroll
            for (int mt = 0; mt < 4; mt++) {
                int arow = wm + mt * 16 + amoff + (lane & 7);
                ldsm_x4(a[mt], abase + arow * 128 + ((ks * 32 + akoff) ^ ((arow & 7) * 16)));
            }
            #pragma unroll
            for (int nt2 = 0; nt2 < 2; nt2++) {
                int brow = wn + nt2 * 16 + bnoff + (lane & 7);
                ldsm_x4(b[nt2], bbase + brow * 128 + ((ks * 32 + bkoff) ^ ((brow & 7) * 16)));
            }
            #pragma unroll
            for (int mt = 0; mt < 4; mt++)
                #pragma unroll
                for (int nt = 0; nt < 4; nt++)
                    mma16816(acc[mt][nt], a[mt], b[nt >> 1][(nt & 1) * 2],
                             b[nt >> 1][(nt & 1) * 2 + 1]);
        }
    };

    ldgB(0);
    cpA(0, 0);
    CP_COMMIT();
    CP_WAIT0();
    stsB(0);
    __syncthreads();
    for (int c = 0; c < FEAT / BK; c++) {
        int cur = c & 1;
        if (c < FEAT / BK - 1) { ldgB(c + 1); cpA(c + 1, cur ^ 1); CP_COMMIT(); }
        compute(cur);
        if (c < FEAT / BK - 1) { CP_WAIT0(); stsB(cur ^ 1); }
        __syncthreads();
    }

    // ---- epilogue: bf16 score stores ----
    #pragma unroll
    for (int mt = 0; mt < 4; mt++) {
        int r0 = wm + mt * 16 + (lane >> 2);
        #pragma unroll
        for (int nt = 0; nt < 4; nt++) {
            int col = n0 + wn + nt * 8 + (lane & 3) * 2;
            u32 w0 = f2bf2(acc[mt][nt][0], acc[mt][nt][1]);
            u32 w1 = f2bf2(acc[mt][nt][2], acc[mt][nt][3]);
            *reinterpret_cast<u32*>(&g_sbf[(size_t)r0 * MEM_SIZE + col]) = w0;
            *reinterpret_cast<u32*>(&g_sbf[(size_t)(r0 + 8) * MEM_SIZE + col]) = w1;
        }
    }
}

// ---------------- 3) candidate select on bf16 approx scores ----------------
__device__ __forceinline__ u32 fkey(float f) {
    u32 u = __float_as_uint(f);
    return (u & 0x80000000u) ? ~u : (u | 0x80000000u);
}

__global__ __launch_bounds__(1024) void cand_select() {
    int b = blockIdx.x;
    const uint4* row4 = reinterpret_cast<const uint4*>(g_sbf + (size_t)b * MEM_SIZE);
    __shared__ u32 hist[2048];
    __shared__ float s_thresh;
    for (int i = threadIdx.x; i < 2048; i += blockDim.x) hist[i] = 0;
    if (threadIdx.x == 0) g_cand_cnt[b] = 0;
    __syncthreads();

    for (int i = threadIdx.x; i < MEM_SIZE / 8; i += blockDim.x) {
        uint4 v = row4[i];
        u32 ws[4] = {v.x, v.y, v.z, v.w};
        #pragma unroll
        for (int j = 0; j < 4; j++) {
            float2 f = __bfloat1622float2(*reinterpret_cast<__nv_bfloat162*>(&ws[j]));
            atomicAdd(&hist[fkey(f.x) >> 21], 1);
            atomicAdd(&hist[fkey(f.y) >> 21], 1);
        }
    }
    __syncthreads();
    if (threadIdx.x == 0) {
        u32 cum = 0; int t = 0;
        for (int bin = 2047; bin >= 0; bin--) {
            cum += hist[bin];
            if (cum >= TOPK) { t = bin; break; }
        }
        u32 k = (u32)t << 21;
        float edge = (k & 0x80000000u) ? __uint_as_float(k ^ 0x80000000u)
                                       : __uint_as_float(~k);
        s_thresh = edge - 3.0e-3f;
    }
    __syncthreads();
    float th = s_thresh;

    for (int i = threadIdx.x; i < MEM_SIZE / 8; i += blockDim.x) {
        uint4 v = row4[i];
        u32 ws[4] = {v.x, v.y, v.z, v.w};
        #pragma unroll
        for (int j = 0; j < 4; j++) {
            float2 f = __bfloat1622float2(*reinterpret_cast<__nv_bfloat162*>(&ws[j]));
            if (f.x > th) {
                int p = atomicAdd(&g_cand_cnt[b], 1);
                if (p < CAND_CAP) g_cand_idx[b * CAND_CAP + p] = i * 8 + j * 2;
            }
            if (f.y > th) {
                int p = atomicAdd(&g_cand_cnt[b], 1);
                if (p < CAND_CAP) g_cand_idx[b * CAND_CAP + p] = i * 8 + j * 2 + 1;
            }
        }
    }
}

// ---------------- 4) exact fp32 rescore (warp-coalesced, sequential-k order!)
// One candidate per WARP: lanes load the key row coalesced into a per-warp
// SMEM row, then all lanes redundantly run the ascending-j float4 fma chain
// (broadcast LDS). The accumulation order is IDENTICAL to R7's passing chain.
// Two candidates interleaved per warp to cover fma-chain latency.
#define RES_SMEM (CAND_CAP * 12 + FEAT * 4 + 64 * FEAT * 4)   // 182272 B

__global__ __launch_bounds__(1024) void rescore_rank(const float* __restrict__ sk,
                                                     float* __restrict__ out_score,
                                                     float* __restrict__ out_index) {
    int b = blockIdx.x;
    extern __shared__ __align__(16) char rsm[];
    u64*   s_key  = reinterpret_cast<u64*>(rsm);                       // 32 KB
    float* s_sc   = reinterpret_cast<float*>(rsm + CAND_CAP * 8);      // 16 KB
    float* s_q    = reinterpret_cast<float*>(rsm + CAND_CAP * 12);     // 2 KB
    float* s_rows = reinterpret_cast<float*>(rsm + CAND_CAP * 12 + FEAT * 4); // 64 rows
    for (int i = threadIdx.x; i < FEAT; i += blockDim.x) s_q[i] = g_qn[(size_t)b * FEAT + i];
    __syncthreads();

    int n = g_cand_cnt[b];
    if (n > CAND_CAP) n = CAND_CAP;
    int w = threadIdx.x >> 5, l = threadIdx.x & 31;
    float4* rowA = reinterpret_cast<float4*>(s_rows + (2 * w) * FEAT);
    float4* rowB = reinterpret_cast<float4*>(s_rows + (2 * w + 1) * FEAT);
    const float4* q4 = reinterpret_cast<const float4*>(s_q);

    for (int t = w; t < n; t += 64) {
        int ciA = t, ciB = t + 32;
        bool hasB = (ciB < n);
        int idxA = g_cand_idx[b * CAND_CAP + ciA];
        const float4* krA = reinterpret_cast<const float4*>(sk + (size_t)idxA * FEAT);
        #pragma unroll
        for (int s = 0; s < 4; s++) rowA[l + 32 * s] = krA[l + 32 * s];
        int idxB = idxA;
        if (hasB) {
            idxB = g_cand_idx[b * CAND_CAP + ciB];
            const float4* krB = reinterpret_cast<const float4*>(sk + (size_t)idxB * FEAT);
            #pragma unroll
            for (int s = 0; s < 4; s++) rowB[l + 32 * s] = krB[l + 32 * s];
        }
        __syncwarp();
        float aA = 0.f, aB = 0.f;
        #pragma unroll 8
        for (int j = 0; j < FEAT / 4; j++) {
            float4 qv = q4[j];
            float4 va = rowA[j];
            float4 vb = rowB[j];
            aA = fmaf(qv.x, va.x, aA);
            aB = fmaf(qv.x, vb.x, aB);
            aA = fmaf(qv.y, va.y, aA);
            aB = fmaf(qv.y, vb.y, aB);
            aA = fmaf(qv.z, va.z, aA);
            aB = fmaf(qv.z, vb.z, aB);
            aA = fmaf(qv.w, va.w, aA);
            aB = fmaf(qv.w, vb.w, aB);
        }
        __syncwarp();
        if (l == 0) {
            s_sc[ciA] = aA;
            s_key[ciA] = ((u64)fkey(aA) << 32) | (u32)(0xFFFFFFFFu - (u32)idxA);
            if (hasB) {
                s_sc[ciB] = aB;
                s_key[ciB] = ((u64)fkey(aB) << 32) | (u32)(0xFFFFFFFFu - (u32)idxB);
            }
        }
    }
    __syncthreads();

    for (int ci = threadIdx.x; ci < n; ci += blockDim.x) {
        u64 kc = s_key[ci];
        int rank = 0;
        for (int j = 0; j < n; j++) rank += (s_key[j] > kc);
        if (rank < TOPK) {
            int idx = (int)(0xFFFFFFFFu - (u32)(kc & 0xFFFFFFFFull));
            out_score[b * TOPK + rank] = s_sc[ci];
            out_index[b * TOPK + rank] = (float)idx;
            g_topk_idx[b * TOPK + rank] = idx;
        }
    }
}

// ---------------- 5) gather ----------------
__global__ void gather_kernel(const float* __restrict__ cv, float* __restrict__ out_feat) {
    int r = blockIdx.x;
    int idx = g_topk_idx[r];
    const float4* src = reinterpret_cast<const float4*>(cv + (size_t)idx * FEAT);
    float4* dst = reinterpret_cast<float4*>(out_feat + (size_t)r * FEAT);
    dst[threadIdx.x] = src[threadIdx.x];
}

// ---------------- launch ----------------
extern "C" void kernel_launch(void* const* d_in, const int* in_sizes, int n_in,
                              void* d_out, int out_size) {
    const float* query = (const float*)d_in[0];
    const float* skey  = (const float*)d_in[1];
    const float* cval  = (const float*)d_in[2];
    float* out = (float*)d_out;
    float* out_feat  = out;
    float* out_score = out + (size_t)BATCH * TOPK * FEAT;
    float* out_index = out_score + (size_t)BATCH * TOPK;

    cudaFuncSetAttribute(score_gemm_mma, cudaFuncAttributeMaxDynamicSharedMemorySize, GEMM_SMEM);
    cudaFuncSetAttribute(rescore_rank, cudaFuncAttributeMaxDynamicSharedMemorySize, RES_SMEM);

    qnorm_kernel<<<BATCH, 128>>>(query);
    score_gemm_mma<<<MEM_SIZE / 128, 256, GEMM_SMEM>>>(skey);
    cand_select<<<BATCH, 1024>>>();
    rescore_rank<<<BATCH, 1024, RES_SMEM>>>(skey, out_score, out_index);
    gather_kernel<<<BATCH * TOPK, 128>>>(cval, out_feat);
}

// round 9
// speedup vs baseline: 1.5211x; 1.5211x over previous
#include <cuda_runtime.h>
#include <cuda_bf16.h>
#include <cstdint>

#define MEM_SIZE 262144
#define FEAT 512
#define TOPK 256
#define BATCH 128
#define CAND_CAP 4096

typedef unsigned long long u64;
typedef unsigned int u32;

// ---------------- scratch (static __device__, no allocation) ----------------
__device__ __align__(16) float g_qn[BATCH * FEAT];
__device__ __align__(16) __nv_bfloat16 g_qbf[BATCH * FEAT];
__device__ __align__(16) __nv_bfloat16 g_sbf[(size_t)BATCH * MEM_SIZE];  // approx scores, bf16
__device__ int   g_cand_idx[BATCH * CAND_CAP];
__device__ int   g_cand_cnt[BATCH];
__device__ int   g_topk_idx[BATCH * TOPK];

// ---------------- helpers ----------------
__device__ __forceinline__ uint32_t smem_u32(const void* p) {
    uint32_t a;
    asm("{ .reg .u64 t; cvta.to.shared.u64 t, %1; cvt.u32.u64 %0, t; }" : "=r"(a) : "l"(p));
    return a;
}
__device__ __forceinline__ u32 f2bf2(float lo, float hi) {
    u32 r; asm("cvt.rn.bf16x2.f32 %0, %1, %2;" : "=r"(r) : "f"(hi), "f"(lo)); return r;
}
__device__ __forceinline__ u32 swz(u32 off) { return off ^ ((off >> 3) & 0x70u); }

__device__ __forceinline__ void ldsm_x4(u32* r, u32 addr) {
    asm volatile("ldmatrix.sync.aligned.m8n8.x4.shared.b16 {%0,%1,%2,%3}, [%4];"
                 : "=r"(r[0]), "=r"(r[1]), "=r"(r[2]), "=r"(r[3]) : "r"(addr));
}
__device__ __forceinline__ void mma16816(float* c, const u32* a, u32 b0, u32 b1) {
    asm volatile(
        "mma.sync.aligned.m16n8k16.row.col.f32.bf16.bf16.f32 "
        "{%0,%1,%2,%3}, {%4,%5,%6,%7}, {%8,%9}, {%0,%1,%2,%3};"
        : "+f"(c[0]), "+f"(c[1]), "+f"(c[2]), "+f"(c[3])
        : "r"(a[0]), "r"(a[1]), "r"(a[2]), "r"(a[3]), "r"(b0), "r"(b1));
}
__device__ __forceinline__ void cp_async16(u32 dst, const void* src) {
    u64 g = (u64)__cvta_generic_to_global(src);
    asm volatile("cp.async.cg.shared.global [%0], [%1], 16;" :: "r"(dst), "l"(g) : "memory");
}
#define CP_COMMIT() asm volatile("cp.async.commit_group;" ::: "memory")
#define CP_WAIT0()  asm volatile("cp.async.wait_group 0;" ::: "memory")

// ---------------- 1) query L2 normalize + bf16 copy ----------------
__global__ void qnorm_kernel(const float* __restrict__ q) {
    int b = blockIdx.x;
    const float* row = q + (size_t)b * FEAT;
    float s = 0.f;
    for (int i = threadIdx.x; i < FEAT; i += blockDim.x) { float v = row[i]; s += v * v; }
    __shared__ float red[32];
    int lane = threadIdx.x & 31, wid = threadIdx.x >> 5;
    #pragma unroll
    for (int o = 16; o > 0; o >>= 1) s += __shfl_xor_sync(0xFFFFFFFFu, s, o);
    if (lane == 0) red[wid] = s;
    __syncthreads();
    if (wid == 0) {
        s = (lane < (int)(blockDim.x >> 5)) ? red[lane] : 0.f;
        #pragma unroll
        for (int o = 16; o > 0; o >>= 1) s += __shfl_xor_sync(0xFFFFFFFFu, s, o);
        if (lane == 0) red[0] = s;
    }
    __syncthreads();
    float inv = 1.0f / sqrtf(red[0]);
    for (int i = threadIdx.x; i < FEAT; i += blockDim.x) {
        float v = row[i] * inv;
        g_qn[(size_t)b * FEAT + i] = v;
        g_qbf[(size_t)b * FEAT + i] = __float2bfloat16(v);
    }
}

// ---------------- 2) bf16 mma.sync score GEMM ----------------
#define BK 64
#define A_TILE 16384
#define B_TILE 16384
#define GEMM_SMEM (2 * A_TILE + 2 * B_TILE)   // 64 KB

__global__ __launch_bounds__(256, 2) void score_gemm_mma(const float* __restrict__ sk) {
    extern __shared__ __align__(1024) char smem[];
    const int tid = threadIdx.x;
    const int wid = tid >> 5, lane = tid & 31;
    const int wm = (wid & 1) * 64;
    const int wn = (wid >> 1) * 32;
    const int n0 = blockIdx.x * 128;
    const u32 sbase = smem_u32(smem);

    float acc[4][4][4];
    #pragma unroll
    for (int i = 0; i < 4; i++)
        #pragma unroll
        for (int j = 0; j < 4; j++)
            #pragma unroll
            for (int k = 0; k < 4; k++) acc[i][j][k] = 0.f;

    float4 st[4][2];

    auto ldgB = [&](int c) {
        #pragma unroll
        for (int it = 0; it < 4; it++) {
            int id = tid + it * 256;
            int r = id >> 3, c32 = id & 7;
            const float4* p = reinterpret_cast<const float4*>(
                sk + (size_t)(n0 + r) * FEAT + c * BK + c32 * 8);
            st[it][0] = p[0]; st[it][1] = p[1];
        }
    };
    auto stsB = [&](int buf) {
        char* bb = smem + 2 * A_TILE + buf * B_TILE;
        #pragma unroll
        for (int it = 0; it < 4; it++) {
            int id = tid + it * 256;
            int r = id >> 3, c32 = id & 7;
            uint4 o;
            o.x = f2bf2(st[it][0].x, st[it][0].y);
            o.y = f2bf2(st[it][0].z, st[it][0].w);
            o.z = f2bf2(st[it][1].x, st[it][1].y);
            o.w = f2bf2(st[it][1].z, st[it][1].w);
            *reinterpret_cast<uint4*>(bb + swz(r * 128 + c32 * 16)) = o;
        }
    };
    auto cpA = [&](int c, int buf) {
        const char* src0 = reinterpret_cast<const char*>(g_qbf);
        u32 dst0 = sbase + buf * A_TILE;
        #pragma unroll
        for (int it = 0; it < 4; it++) {
            int id = tid + it * 256;
            int r = id >> 3, c16 = id & 7;
            cp_async16(dst0 + swz(r * 128 + c16 * 16),
                       src0 + r * 1024 + c * 128 + c16 * 16);
        }
    };

    const int jj = lane >> 3;
    const int akoff = (jj >= 2) ? 16 : 0;
    const int amoff = (jj & 1) * 8;
    const int bnoff = (jj >= 2) ? 8 : 0;
    const int bkoff = (jj & 1) * 16;
    auto compute = [&](int buf) {
        u32 abase = sbase + buf * A_TILE;
        u32 bbase = sbase + 2 * A_TILE + buf * B_TILE;
        #pragma unroll
        for (int ks = 0; ks < 4; ks++) {
            u32 a[4][4], b[2][4];
            #pragma unroll
            for (int mt = 0; mt < 4; mt++) {
                int arow = wm + mt * 16 + amoff + (lane & 7);
                ldsm_x4(a[mt], abase + arow * 128 + ((ks * 32 + akoff) ^ ((arow & 7) * 16)));
            }
            #pragma unroll
            for (int nt2 = 0; nt2 < 2; nt2++) {
                int brow = wn + nt2 * 16 + bnoff + (lane & 7);
                ldsm_x4(b[nt2], bbase + brow * 128 + ((ks * 32 + bkoff) ^ ((brow & 7) * 16)));
            }
            #pragma unroll
            for (int mt = 0; mt < 4; mt++)
                #pragma unroll
                for (int nt = 0; nt < 4; nt++)
                    mma16816(acc[mt][nt], a[mt], b[nt >> 1][(nt & 1) * 2],
                             b[nt >> 1][(nt & 1) * 2 + 1]);
        }
    };

    ldgB(0);
    cpA(0, 0);
    CP_COMMIT();
    CP_WAIT0();
    stsB(0);
    __syncthreads();
    for (int c = 0; c < FEAT / BK; c++) {
        int cur = c & 1;
        if (c < FEAT / BK - 1) { ldgB(c + 1); cpA(c + 1, cur ^ 1); CP_COMMIT(); }
        compute(cur);
        if (c < FEAT / BK - 1) { CP_WAIT0(); stsB(cur ^ 1); }
        __syncthreads();
    }

    // ---- epilogue: bf16 score stores ----
    #pragma unroll
    for (int mt = 0; mt < 4; mt++) {
        int r0 = wm + mt * 16 + (lane >> 2);
        #pragma unroll
        for (int nt = 0; nt < 4; nt++) {
            int col = n0 + wn + nt * 8 + (lane & 3) * 2;
            u32 w0 = f2bf2(acc[mt][nt][0], acc[mt][nt][1]);
            u32 w1 = f2bf2(acc[mt][nt][2], acc[mt][nt][3]);
            *reinterpret_cast<u32*>(&g_sbf[(size_t)r0 * MEM_SIZE + col]) = w0;
            *reinterpret_cast<u32*>(&g_sbf[(size_t)(r0 + 8) * MEM_SIZE + col]) = w1;
        }
    }
}

// ---------------- 3) candidate select on bf16 approx scores ----------------
__device__ __forceinline__ u32 fkey(float f) {
    u32 u = __float_as_uint(f);
    return (u & 0x80000000u) ? ~u : (u | 0x80000000u);
}

__global__ __launch_bounds__(1024) void cand_select() {
    int b = blockIdx.x;
    const uint4* row4 = reinterpret_cast<const uint4*>(g_sbf + (size_t)b * MEM_SIZE);
    __shared__ u32 hist[2048];
    __shared__ float s_thresh;
    for (int i = threadIdx.x; i < 2048; i += blockDim.x) hist[i] = 0;
    if (threadIdx.x == 0) g_cand_cnt[b] = 0;
    __syncthreads();

    for (int i = threadIdx.x; i < MEM_SIZE / 8; i += blockDim.x) {
        uint4 v = row4[i];
        u32 ws[4] = {v.x, v.y, v.z, v.w};
        #pragma unroll
        for (int j = 0; j < 4; j++) {
            float2 f = __bfloat1622float2(*reinterpret_cast<__nv_bfloat162*>(&ws[j]));
            atomicAdd(&hist[fkey(f.x) >> 21], 1);
            atomicAdd(&hist[fkey(f.y) >> 21], 1);
        }
    }
    __syncthreads();
    if (threadIdx.x == 0) {
        u32 cum = 0; int t = 0;
        for (int bin = 2047; bin >= 0; bin--) {
            cum += hist[bin];
            if (cum >= TOPK) { t = bin; break; }
        }
        u32 k = (u32)t << 21;
        float edge = (k & 0x80000000u) ? __uint_as_float(k ^ 0x80000000u)
                                       : __uint_as_float(~k);
        s_thresh = edge - 3.0e-3f;
    }
    __syncthreads();
    float th = s_thresh;

    for (int i = threadIdx.x; i < MEM_SIZE / 8; i += blockDim.x) {
        uint4 v = row4[i];
        u32 ws[4] = {v.x, v.y, v.z, v.w};
        #pragma unroll
        for (int j = 0; j < 4; j++) {
            float2 f = __bfloat1622float2(*reinterpret_cast<__nv_bfloat162*>(&ws[j]));
            if (f.x > th) {
                int p = atomicAdd(&g_cand_cnt[b], 1);
                if (p < CAND_CAP) g_cand_idx[b * CAND_CAP + p] = i * 8 + j * 2;
            }
            if (f.y > th) {
                int p = atomicAdd(&g_cand_cnt[b], 1);
                if (p < CAND_CAP) g_cand_idx[b * CAND_CAP + p] = i * 8 + j * 2 + 1;
            }
        }
    }
}

// ---------------- 4) exact fp32 rescore + exact rank ----------------
// One candidate per THREAD (no redundant compute), but the key rows are staged
// cooperatively per warp into padded SMEM with fully coalesced global loads
// (1 wavefront per 128B line, the minimum). Each thread then accumulates ITS
// candidate's dot in pure ascending-k fmaf order — the exact chain that has
// passed since R1. Chunked (32 floats) with register prefetch of next chunk.
#define WCH 32
#define NCHK (FEAT / WCH)     // 16
#define RPAD 33               // stride pad: banks (l+k)%32 conflict-free
#define RES_SMEM (CAND_CAP * 8 + CAND_CAP * 4 + FEAT * 4 + 32 * 32 * RPAD * 4) // 186368

__global__ __launch_bounds__(1024) void rescore_rank(const float* __restrict__ sk,
                                                     float* __restrict__ out_score,
                                                     float* __restrict__ out_index) {
    int b = blockIdx.x;
    extern __shared__ __align__(16) char rsm[];
    u64*   s_key = reinterpret_cast<u64*>(rsm);                    // 32 KB
    float* s_sc  = reinterpret_cast<float*>(rsm + CAND_CAP * 8);   // 16 KB
    float* s_q   = reinterpret_cast<float*>(rsm + CAND_CAP * 12);  // 2 KB
    float* s_rows_all = reinterpret_cast<float*>(rsm + CAND_CAP * 12 + FEAT * 4);
    for (int i = threadIdx.x; i < FEAT; i += blockDim.x) s_q[i] = g_qn[(size_t)b * FEAT + i];
    __syncthreads();

    int n = g_cand_cnt[b];
    if (n > CAND_CAP) n = CAND_CAP;
    const int w = threadIdx.x >> 5, l = threadIdx.x & 31;
    float* srow = s_rows_all + w * (32 * RPAD);
    const int srr = l >> 3;       // staging row-in-quad
    const int sf4 = l & 7;        // staging float4 slot

    for (int base = w * 32; base < n; base += 1024) {
        int ci = base + l;
        bool valid = (ci < n);
        int cidx = g_cand_idx[b * CAND_CAP + (valid ? ci : base)];
        // gather the 8 row indices this lane stages (rows srr, srr+4, ..., srr+28)
        u32 rowidx[8];
        #pragma unroll
        for (int rr = 0; rr < 8; rr++)
            rowidx[rr] = (u32)__shfl_sync(0xFFFFFFFFu, cidx, rr * 4 + srr);

        float4 stg[8];
        #pragma unroll
        for (int rr = 0; rr < 8; rr++)
            stg[rr] = reinterpret_cast<const float4*>(sk + (size_t)rowidx[rr] * FEAT)[sf4];

        float acc = 0.f;
        for (int c = 0; c < NCHK; c++) {
            // store staged chunk c (scalar STS, conflict-free)
            #pragma unroll
            for (int rr = 0; rr < 8; rr++) {
                float* d = srow + (rr * 4 + srr) * RPAD + sf4 * 4;
                d[0] = stg[rr].x; d[1] = stg[rr].y; d[2] = stg[rr].z; d[3] = stg[rr].w;
            }
            __syncwarp();
            // prefetch chunk c+1 (coalesced: 8 lanes cover one 128B line)
            if (c + 1 < NCHK) {
                #pragma unroll
                for (int rr = 0; rr < 8; rr++)
                    stg[rr] = reinterpret_cast<const float4*>(
                        sk + (size_t)rowidx[rr] * FEAT)[(c + 1) * 8 + sf4];
            }
            // compute chunk c: thread l -> staged row l, ascending k
            const float* qc = s_q + c * WCH;
            const float* rl = srow + l * RPAD;
            #pragma unroll
            for (int k = 0; k < WCH; k++) acc = fmaf(qc[k], rl[k], acc);
            __syncwarp();
        }
        if (valid) {
            s_sc[ci] = acc;
            s_key[ci] = ((u64)fkey(acc) << 32) | (u32)(0xFFFFFFFFu - (u32)cidx);
        }
    }
    __syncthreads();

    for (int ci = threadIdx.x; ci < n; ci += blockDim.x) {
        u64 kc = s_key[ci];
        int rank = 0;
        for (int j = 0; j < n; j++) rank += (s_key[j] > kc);
        if (rank < TOPK) {
            int idx = (int)(0xFFFFFFFFu - (u32)(kc & 0xFFFFFFFFull));
            out_score[b * TOPK + rank] = s_sc[ci];
            out_index[b * TOPK + rank] = (float)idx;
            g_topk_idx[b * TOPK + rank] = idx;
        }
    }
}

// ---------------- 5) gather ----------------
__global__ void gather_kernel(const float* __restrict__ cv, float* __restrict__ out_feat) {
    int r = blockIdx.x;
    int idx = g_topk_idx[r];
    const float4* src = reinterpret_cast<const float4*>(cv + (size_t)idx * FEAT);
    float4* dst = reinterpret_cast<float4*>(out_feat + (size_t)r * FEAT);
    dst[threadIdx.x] = src[threadIdx.x];
}

// ---------------- launch ----------------
extern "C" void kernel_launch(void* const* d_in, const int* in_sizes, int n_in,
                              void* d_out, int out_size) {
    const float* query = (const float*)d_in[0];
    const float* skey  = (const float*)d_in[1];
    const float* cval  = (const float*)d_in[2];
    float* out = (float*)d_out;
    float* out_feat  = out;
    float* out_score = out + (size_t)BATCH * TOPK * FEAT;
    float* out_index = out_score + (size_t)BATCH * TOPK;

    cudaFuncSetAttribute(score_gemm_mma, cudaFuncAttributeMaxDynamicSharedMemorySize, GEMM_SMEM);
    cudaFuncSetAttribute(rescore_rank, cudaFuncAttributeMaxDynamicSharedMemorySize, RES_SMEM);

    qnorm_kernel<<<BATCH, 128>>>(query);
    score_gemm_mma<<<MEM_SIZE / 128, 256, GEMM_SMEM>>>(skey);
    cand_select<<<BATCH, 1024>>>();
    rescore_rank<<<BATCH, 1024, RES_SMEM>>>(skey, out_score, out_index);
    gather_kernel<<<BATCH * TOPK, 128>>>(cval, out_feat);
}

// round 10
// speedup vs baseline: 1.9210x; 1.2629x over previous
#include <cuda_runtime.h>
#include <cuda_bf16.h>
#include <cstdint>

#define MEM_SIZE 262144
#define FEAT 512
#define TOPK 256
#define BATCH 128
#define CAND_CAP 4096
#define NBIN 8192

typedef unsigned long long u64;
typedef unsigned int u32;

// ---------------- scratch (static __device__, no allocation) ----------------
__device__ __align__(16) float g_qn[BATCH * FEAT];
__device__ __align__(16) __nv_bfloat16 g_qbf[BATCH * FEAT];
__device__ __align__(16) __nv_bfloat16 g_sbf[(size_t)BATCH * MEM_SIZE];  // approx scores, bf16
__device__ int   g_cand_idx[BATCH * CAND_CAP];
__device__ int   g_cand_cnt[BATCH];

// ---------------- helpers ----------------
__device__ __forceinline__ uint32_t smem_u32(const void* p) {
    uint32_t a;
    asm("{ .reg .u64 t; cvta.to.shared.u64 t, %1; cvt.u32.u64 %0, t; }" : "=r"(a) : "l"(p));
    return a;
}
__device__ __forceinline__ u32 f2bf2(float lo, float hi) {
    u32 r; asm("cvt.rn.bf16x2.f32 %0, %1, %2;" : "=r"(r) : "f"(hi), "f"(lo)); return r;
}
__device__ __forceinline__ u32 swz(u32 off) { return off ^ ((off >> 3) & 0x70u); }

__device__ __forceinline__ void ldsm_x4(u32* r, u32 addr) {
    asm volatile("ldmatrix.sync.aligned.m8n8.x4.shared.b16 {%0,%1,%2,%3}, [%4];"
                 : "=r"(r[0]), "=r"(r[1]), "=r"(r[2]), "=r"(r[3]) : "r"(addr));
}
__device__ __forceinline__ void mma16816(float* c, const u32* a, u32 b0, u32 b1) {
    asm volatile(
        "mma.sync.aligned.m16n8k16.row.col.f32.bf16.bf16.f32 "
        "{%0,%1,%2,%3}, {%4,%5,%6,%7}, {%8,%9}, {%0,%1,%2,%3};"
        : "+f"(c[0]), "+f"(c[1]), "+f"(c[2]), "+f"(c[3])
        : "r"(a[0]), "r"(a[1]), "r"(a[2]), "r"(a[3]), "r"(b0), "r"(b1));
}
__device__ __forceinline__ void cp_async16(u32 dst, const void* src) {
    u64 g = (u64)__cvta_generic_to_global(src);
    asm volatile("cp.async.cg.shared.global [%0], [%1], 16;" :: "r"(dst), "l"(g) : "memory");
}
#define CP_COMMIT() asm volatile("cp.async.commit_group;" ::: "memory")
#define CP_WAIT0()  asm volatile("cp.async.wait_group 0;" ::: "memory")

// ---------------- 1) query L2 normalize + bf16 copy ----------------
__global__ void qnorm_kernel(const float* __restrict__ q) {
    int b = blockIdx.x;
    const float* row = q + (size_t)b * FEAT;
    float s = 0.f;
    for (int i = threadIdx.x; i < FEAT; i += blockDim.x) { float v = row[i]; s += v * v; }
    __shared__ float red[32];
    int lane = threadIdx.x & 31, wid = threadIdx.x >> 5;
    #pragma unroll
    for (int o = 16; o > 0; o >>= 1) s += __shfl_xor_sync(0xFFFFFFFFu, s, o);
    if (lane == 0) red[wid] = s;
    __syncthreads();
    if (wid == 0) {
        s = (lane < (int)(blockDim.x >> 5)) ? red[lane] : 0.f;
        #pragma unroll
        for (int o = 16; o > 0; o >>= 1) s += __shfl_xor_sync(0xFFFFFFFFu, s, o);
        if (lane == 0) red[0] = s;
    }
    __syncthreads();
    float inv = 1.0f / sqrtf(red[0]);
    for (int i = threadIdx.x; i < FEAT; i += blockDim.x) {
        float v = row[i] * inv;
        g_qn[(size_t)b * FEAT + i] = v;
        g_qbf[(size_t)b * FEAT + i] = __float2bfloat16(v);
    }
}

// ---------------- 2) bf16 mma.sync score GEMM ----------------
#define BK 64
#define A_TILE 16384
#define B_TILE 16384
#define GEMM_SMEM (2 * A_TILE + 2 * B_TILE)   // 64 KB

__global__ __launch_bounds__(256, 2) void score_gemm_mma(const float* __restrict__ sk) {
    extern __shared__ __align__(1024) char smem[];
    const int tid = threadIdx.x;
    const int wid = tid >> 5, lane = tid & 31;
    const int wm = (wid & 1) * 64;
    const int wn = (wid >> 1) * 32;
    const int n0 = blockIdx.x * 128;
    const u32 sbase = smem_u32(smem);

    float acc[4][4][4];
    #pragma unroll
    for (int i = 0; i < 4; i++)
        #pragma unroll
        for (int j = 0; j < 4; j++)
            #pragma unroll
            for (int k = 0; k < 4; k++) acc[i][j][k] = 0.f;

    float4 st4[8];   // B fp32 staging: one float4 per load instr, fully coalesced

    auto ldgB = [&](int c) {
        #pragma unroll
        for (int it = 0; it < 8; it++) {
            int id = tid + it * 256;        // 0..2047 float4-granules of the 32KB chunk
            int r = id >> 4, g = id & 15;   // row 0..127, float4 slot 0..15
            st4[it] = reinterpret_cast<const float4*>(
                sk + (size_t)(n0 + r) * FEAT + c * BK)[g];
        }
    };
    auto stsB = [&](int buf) {
        char* bb = smem + 2 * A_TILE + buf * B_TILE;
        #pragma unroll
        for (int it = 0; it < 8; it++) {
            int id = tid + it * 256;
            int r = id >> 4, g = id & 15;
            uint2 o;
            o.x = f2bf2(st4[it].x, st4[it].y);
            o.y = f2bf2(st4[it].z, st4[it].w);
            *reinterpret_cast<uint2*>(bb + swz(r * 128 + g * 8)) = o;
        }
    };
    auto cpA = [&](int c, int buf) {
        const char* src0 = reinterpret_cast<const char*>(g_qbf);
        u32 dst0 = sbase + buf * A_TILE;
        #pragma unroll
        for (int it = 0; it < 4; it++) {
            int id = tid + it * 256;
            int r = id >> 3, c16 = id & 7;
            cp_async16(dst0 + swz(r * 128 + c16 * 16),
                       src0 + r * 1024 + c * 128 + c16 * 16);
        }
    };

    const int jj = lane >> 3;
    const int akoff = (jj >= 2) ? 16 : 0;
    const int amoff = (jj & 1) * 8;
    const int bnoff = (jj >= 2) ? 8 : 0;
    const int bkoff = (jj & 1) * 16;
    auto compute = [&](int buf) {
        u32 abase = sbase + buf * A_TILE;
        u32 bbase = sbase + 2 * A_TILE + buf * B_TILE;
        #pragma unroll
        for (int ks = 0; ks < 4; ks++) {
            u32 a[4][4], b[2][4];
            #pragma unroll
            for (int mt = 0; mt < 4; mt++) {
                int arow = wm + mt * 16 + amoff + (lane & 7);
                ldsm_x4(a[mt], abase + arow * 128 + ((ks * 32 + akoff) ^ ((arow & 7) * 16)));
            }
            #pragma unroll
            for (int nt2 = 0; nt2 < 2; nt2++) {
                int brow = wn + nt2 * 16 + bnoff + (lane & 7);
                ldsm_x4(b[nt2], bbase + brow * 128 + ((ks * 32 + bkoff) ^ ((brow & 7) * 16)));
            }
            #pragma unroll
            for (int mt = 0; mt < 4; mt++)
                #pragma unroll
                for (int nt = 0; nt < 4; nt++)
                    mma16816(acc[mt][nt], a[mt], b[nt >> 1][(nt & 1) * 2],
                             b[nt >> 1][(nt & 1) * 2 + 1]);
        }
    };

    ldgB(0);
    cpA(0, 0);
    CP_COMMIT();
    CP_WAIT0();
    stsB(0);
    __syncthreads();
    for (int c = 0; c < FEAT / BK; c++) {
        int cur = c & 1;
        if (c < FEAT / BK - 1) { ldgB(c + 1); cpA(c + 1, cur ^ 1); CP_COMMIT(); }
        compute(cur);
        if (c < FEAT / BK - 1) { CP_WAIT0(); stsB(cur ^ 1); }
        __syncthreads();
    }

    // ---- epilogue: bf16 score stores ----
    #pragma unroll
    for (int mt = 0; mt < 4; mt++) {
        int r0 = wm + mt * 16 + (lane >> 2);
        #pragma unroll
        for (int nt = 0; nt < 4; nt++) {
            int col = n0 + wn + nt * 8 + (lane & 3) * 2;
            u32 w0 = f2bf2(acc[mt][nt][0], acc[mt][nt][1]);
            u32 w1 = f2bf2(acc[mt][nt][2], acc[mt][nt][3]);
            *reinterpret_cast<u32*>(&g_sbf[(size_t)r0 * MEM_SIZE + col]) = w0;
            *reinterpret_cast<u32*>(&g_sbf[(size_t)(r0 + 8) * MEM_SIZE + col]) = w1;
        }
    }
}

// ---------------- 3) candidate select (8192-bin histogram) ----------------
__device__ __forceinline__ u32 fkey(float f) {
    u32 u = __float_as_uint(f);
    return (u & 0x80000000u) ? ~u : (u | 0x80000000u);
}

__global__ __launch_bounds__(1024) void cand_select() {
    int b = blockIdx.x;
    const uint4* row4 = reinterpret_cast<const uint4*>(g_sbf + (size_t)b * MEM_SIZE);
    __shared__ u32 hist[NBIN];
    __shared__ u32 seg[1024];
    __shared__ float s_thresh;
    for (int i = threadIdx.x; i < NBIN; i += blockDim.x) hist[i] = 0;
    if (threadIdx.x == 0) g_cand_cnt[b] = 0;
    __syncthreads();

    for (int i = threadIdx.x; i < MEM_SIZE / 8; i += blockDim.x) {
        uint4 v = row4[i];
        u32 ws[4] = {v.x, v.y, v.z, v.w};
        #pragma unroll
        for (int j = 0; j < 4; j++) {
            float2 f = __bfloat1622float2(*reinterpret_cast<__nv_bfloat162*>(&ws[j]));
            atomicAdd(&hist[fkey(f.x) >> 19], 1);
            atomicAdd(&hist[fkey(f.y) >> 19], 1);
        }
    }
    __syncthreads();
    // parallel threshold find: 1024 segments of 8 bins
    {
        u32 s = 0;
        #pragma unroll
        for (int j = 0; j < 8; j++) s += hist[threadIdx.x * 8 + j];
        seg[threadIdx.x] = s;
    }
    __syncthreads();
    if (threadIdx.x == 0) {
        u32 cum = 0; int t = 0;
        for (int sgi = 1023; sgi >= 0; sgi--) {
            if (cum + seg[sgi] >= TOPK) {
                for (int bin = sgi * 8 + 7; bin >= sgi * 8; bin--) {
                    cum += hist[bin];
                    if (cum >= TOPK) { t = bin; break; }
                }
                break;
            }
            cum += seg[sgi];
        }
        u32 k = (u32)t << 19;
        float edge = (k & 0x80000000u) ? __uint_as_float(k ^ 0x80000000u)
                                       : __uint_as_float(~k);
        s_thresh = edge - 2.0e-3f;   // proven margin; bin slack now only ~2e-3
    }
    __syncthreads();
    float th = s_thresh;

    for (int i = threadIdx.x; i < MEM_SIZE / 8; i += blockDim.x) {
        uint4 v = row4[i];
        u32 ws[4] = {v.x, v.y, v.z, v.w};
        #pragma unroll
        for (int j = 0; j < 4; j++) {
            float2 f = __bfloat1622float2(*reinterpret_cast<__nv_bfloat162*>(&ws[j]));
            if (f.x > th) {
                int p = atomicAdd(&g_cand_cnt[b], 1);
                if (p < CAND_CAP) g_cand_idx[b * CAND_CAP + p] = i * 8 + j * 2;
            }
            if (f.y > th) {
                int p = atomicAdd(&g_cand_cnt[b], 1);
                if (p < CAND_CAP) g_cand_idx[b * CAND_CAP + p] = i * 8 + j * 2 + 1;
            }
        }
    }
}

// ---------------- 4) exact fp32 rescore + rank + fused gather ----------------
// Rescore: one candidate per thread, warp-cooperative coalesced staging,
// pure ascending-k fmaf chain (bit-identical to the passing R7/R9 order).
// Then rank, then the block gathers its 256 color_value rows directly.
#define WCH 32
#define NCHK (FEAT / WCH)     // 16
#define RPAD 33
#define RES_SMEM (CAND_CAP * 8 + CAND_CAP * 4 + FEAT * 4 + 32 * 32 * RPAD * 4 + TOPK * 4)

__global__ __launch_bounds__(1024) void rescore_rank(const float* __restrict__ sk,
                                                     const float* __restrict__ cv,
                                                     float* __restrict__ out_feat,
                                                     float* __restrict__ out_score,
                                                     float* __restrict__ out_index) {
    int b = blockIdx.x;
    extern __shared__ __align__(16) char rsm[];
    u64*   s_key = reinterpret_cast<u64*>(rsm);                    // 32 KB
    float* s_sc  = reinterpret_cast<float*>(rsm + CAND_CAP * 8);   // 16 KB
    float* s_q   = reinterpret_cast<float*>(rsm + CAND_CAP * 12);  // 2 KB
    float* s_rows_all = reinterpret_cast<float*>(rsm + CAND_CAP * 12 + FEAT * 4);
    int*   s_top = reinterpret_cast<int*>(rsm + CAND_CAP * 12 + FEAT * 4 + 32 * 32 * RPAD * 4);
    for (int i = threadIdx.x; i < FEAT; i += blockDim.x) s_q[i] = g_qn[(size_t)b * FEAT + i];
    __syncthreads();

    int n = g_cand_cnt[b];
    if (n > CAND_CAP) n = CAND_CAP;
    const int w = threadIdx.x >> 5, l = threadIdx.x & 31;
    float* srow = s_rows_all + w * (32 * RPAD);
    const int srr = l >> 3;
    const int sf4 = l & 7;

    for (int base = w * 32; base < n; base += 1024) {
        int ci = base + l;
        bool valid = (ci < n);
        int cidx = g_cand_idx[b * CAND_CAP + (valid ? ci : base)];
        u32 rowidx[8];
        #pragma unroll
        for (int rr = 0; rr < 8; rr++)
            rowidx[rr] = (u32)__shfl_sync(0xFFFFFFFFu, cidx, rr * 4 + srr);

        float4 stg[8];
        #pragma unroll
        for (int rr = 0; rr < 8; rr++)
            stg[rr] = reinterpret_cast<const float4*>(sk + (size_t)rowidx[rr] * FEAT)[sf4];

        float acc = 0.f;
        for (int c = 0; c < NCHK; c++) {
            #pragma unroll
            for (int rr = 0; rr < 8; rr++) {
                float* d = srow + (rr * 4 + srr) * RPAD + sf4 * 4;
                d[0] = stg[rr].x; d[1] = stg[rr].y; d[2] = stg[rr].z; d[3] = stg[rr].w;
            }
            __syncwarp();
            if (c + 1 < NCHK) {
                #pragma unroll
                for (int rr = 0; rr < 8; rr++)
                    stg[rr] = reinterpret_cast<const float4*>(
                        sk + (size_t)rowidx[rr] * FEAT)[(c + 1) * 8 + sf4];
            }
            const float* qc = s_q + c * WCH;
            const float* rl = srow + l * RPAD;
            #pragma unroll
            for (int k = 0; k < WCH; k++) acc = fmaf(qc[k], rl[k], acc);
            __syncwarp();
        }
        if (valid) {
            s_sc[ci] = acc;
            s_key[ci] = ((u64)fkey(acc) << 32) | (u32)(0xFFFFFFFFu - (u32)cidx);
        }
    }
    __syncthreads();

    for (int ci = threadIdx.x; ci < n; ci += blockDim.x) {
        u64 kc = s_key[ci];
        int rank = 0;
        for (int j = 0; j < n; j++) rank += (s_key[j] > kc);
        if (rank < TOPK) {
            int idx = (int)(0xFFFFFFFFu - (u32)(kc & 0xFFFFFFFFull));
            out_score[b * TOPK + rank] = s_sc[ci];
            out_index[b * TOPK + rank] = (float)idx;
            s_top[rank] = idx;
        }
    }
    __syncthreads();

    // fused gather: copy 256 color_value rows to out_feat[b]
    const float4* cv4 = reinterpret_cast<const float4*>(cv);
    float4* of4 = reinterpret_cast<float4*>(out_feat) + (size_t)b * TOPK * (FEAT / 4);
    for (int t = threadIdx.x; t < TOPK * (FEAT / 4); t += blockDim.x) {
        int row = t >> 7;          // FEAT/4 = 128 float4 per row
        int f4 = t & 127;
        of4[t] = cv4[(size_t)s_top[row] * (FEAT / 4) + f4];
    }
}

// ---------------- launch ----------------
extern "C" void kernel_launch(void* const* d_in, const int* in_sizes, int n_in,
                              void* d_out, int out_size) {
    const float* query = (const float*)d_in[0];
    const float* skey  = (const float*)d_in[1];
    const float* cval  = (const float*)d_in[2];
    float* out = (float*)d_out;
    float* out_feat  = out;
    float* out_score = out + (size_t)BATCH * TOPK * FEAT;
    float* out_index = out_score + (size_t)BATCH * TOPK;

    cudaFuncSetAttribute(score_gemm_mma, cudaFuncAttributeMaxDynamicSharedMemorySize, GEMM_SMEM);
    cudaFuncSetAttribute(rescore_rank, cudaFuncAttributeMaxDynamicSharedMemorySize, RES_SMEM);

    qnorm_kernel<<<BATCH, 128>>>(query);
    score_gemm_mma<<<MEM_SIZE / 128, 256, GEMM_SMEM>>>(skey);
    cand_select<<<BATCH, 1024>>>();
    rescore_rank<<<BATCH, 1024, RES_SMEM>>>(skey, cval, out_feat, out_score, out_index);
}